// round 7
// baseline (speedup 1.0000x reference)
#include <cuda_runtime.h>

#define CCH 64
#define CO 8
#define WIN 13
#define WPB 8
#define TP 104
#define PADW 20          // xs per-window pitch (floats) -> all-8-window distinct bank quads
#define XROW 160         // WPB*PADW
#define WVP 66           // wvT row pitch (2-way store conflict only; 8B-aligned rows)
#define QKP 12           // qT/kT row pitch (48B)
#define ARP 20           // att row pitch
#define AWS 260          // att window stride = 13*ARP
#define OBP 108          // staged out buffer pitch: all-lane distinct banks for scatter
#define NTHREADS 256
#define NVOX 53248
#define TILES_PER_B 512

// byte offsets into dynamic smem (total 76480 -> 3 CTAs/SM)
#define OFF_XS   0          // 64*160*4 = 40960 ; later aliased as obuf[64][108] (27648)
#define OFF_WVT  40960      // 64*66*4  = 16896
#define OFF_WQ   57856      // 64*8*4   = 2048   (dead after q/k proj)
#define OFF_WK   59904      // 2048               (dead after q/k proj)
#define OFF_ATT  57856      // 8*260*4  = 8320   (aliases wq/wk)
#define OFF_QT   66176      // 104*12*4 = 4992
#define OFF_KT   71168      // 4992
#define OFF_BQ   76160
#define OFF_BK   76192
#define OFF_BV   76224      // 256
#define SMEM_BYTES 76480

typedef unsigned long long u64;

__device__ __forceinline__ u64 fma2(u64 a, u64 b, u64 c) {
    u64 d;
    asm("fma.rn.f32x2 %0, %1, %2, %3;" : "=l"(d) : "l"(a), "l"(b), "l"(c));
    return d;
}
__device__ __forceinline__ u64 mul2(u64 a, u64 b) {
    u64 d;
    asm("mul.rn.f32x2 %0, %1, %2;" : "=l"(d) : "l"(a), "l"(b));
    return d;
}
__device__ __forceinline__ u64 dup2(float x) {
    u64 d; unsigned xi = __float_as_uint(x);
    asm("mov.b64 %0, {%1, %1};" : "=l"(d) : "r"(xi));
    return d;
}
__device__ __forceinline__ float lo2(u64 v) { return __uint_as_float((unsigned)v); }
__device__ __forceinline__ float hi2(u64 v) { return __uint_as_float((unsigned)(v >> 32)); }

__global__ __launch_bounds__(NTHREADS, 3)
void win_attn_kernel(const float* __restrict__ x,
                     const float* __restrict__ wq, const float* __restrict__ bq,
                     const float* __restrict__ wk, const float* __restrict__ bk,
                     const float* __restrict__ wv, const float* __restrict__ bv,
                     float* __restrict__ out) {
    extern __shared__ char smem[];
    float* s_xs  = (float*)(smem + OFF_XS);
    float* obuf  = (float*)(smem + OFF_XS);   // aliases xs once dead
    float* s_wvT = (float*)(smem + OFF_WVT);
    float* s_wq  = (float*)(smem + OFF_WQ);
    float* s_wk  = (float*)(smem + OFF_WK);
    float* s_att = (float*)(smem + OFF_ATT);  // aliases wq/wk once dead
    float* s_qT  = (float*)(smem + OFF_QT);
    float* s_kT  = (float*)(smem + OFF_KT);
    float* s_bq  = (float*)(smem + OFF_BQ);
    float* s_bk  = (float*)(smem + OFF_BK);
    float* s_bv  = (float*)(smem + OFF_BV);

    const int tid  = threadIdx.x;
    const int b    = blockIdx.x / TILES_PER_B;
    const int tile = blockIdx.x % TILES_PER_B;
    const long n0  = (long)tile * TP;

    const float* xb = x   + (long)b * CCH * NVOX + n0;
    float*       ob = out + (long)b * CCH * NVOX + n0;

    // ---- weights (transposed) + biases ----
    for (int i = tid; i < CO * CCH; i += NTHREADS) {
        int o = i / CCH, c = i % CCH;
        s_wq[c * CO + o] = wq[i];
        s_wk[c * CO + o] = wk[i];
    }
    for (int i = tid; i < CCH * CCH; i += NTHREADS) {
        int c = i / CCH, cc = i % CCH;
        s_wvT[cc * WVP + c] = wv[i];
    }
    if (tid < CO)                      s_bq[tid]       = bq[tid];
    if (tid >= 64 && tid < 64 + CO)    s_bk[tid - 64]  = bk[tid - 64];
    if (tid >= 128 && tid < 128 + CCH) s_bv[tid - 128] = bv[tid - 128];

    // ---- x tile -> window-padded smem ----
    for (int i = tid; i < CCH * (TP / 4); i += NTHREADS) {
        int r  = i / (TP / 4);
        int c4 = i % (TP / 4);
        float4 v = *reinterpret_cast<const float4*>(xb + (long)r * NVOX + c4 * 4);
        int p = c4 * 4;
        float vv[4] = {v.x, v.y, v.z, v.w};
#pragma unroll
        for (int u = 0; u < 4; u++) {
            int pp = p + u;
            s_xs[r * XROW + (pp / WIN) * PADW + (pp % WIN)] = vv[u];
        }
    }
    __syncthreads();

    // ---- q/k projection: (o4 = tid&1, r = tid>>1) -> conflict-free xs reads ----
    if (tid < 2 * TP) {
        int o4  = tid & 1;
        int r   = tid >> 1;
        int col = (r / WIN) * PADW + (r % WIN);
        u64 aq01 = *(const u64*)&s_bq[o4 * 4];
        u64 aq23 = *(const u64*)&s_bq[o4 * 4 + 2];
        u64 ak01 = *(const u64*)&s_bk[o4 * 4];
        u64 ak23 = *(const u64*)&s_bk[o4 * 4 + 2];
#pragma unroll 8
        for (int c = 0; c < CCH; c++) {
            u64 xd = dup2(s_xs[c * XROW + col]);
            ulonglong2 q2 = *(const ulonglong2*)&s_wq[c * CO + o4 * 4];
            ulonglong2 k2 = *(const ulonglong2*)&s_wk[c * CO + o4 * 4];
            aq01 = fma2(q2.x, xd, aq01);
            aq23 = fma2(q2.y, xd, aq23);
            ak01 = fma2(k2.x, xd, ak01);
            ak23 = fma2(k2.y, xd, ak23);
        }
        *(ulonglong2*)&s_qT[r * QKP + o4 * 4] = make_ulonglong2(aq01, aq23);
        *(ulonglong2*)&s_kT[r * QKP + o4 * 4] = make_ulonglong2(ak01, ak23);
    }
    __syncthreads();

    // ---- scores: single pass, 8 channels packed (att aliases dead wq/wk) ----
    for (int m = tid; m < WPB * WIN * WIN; m += NTHREADS) {
        int w  = m / (WIN * WIN);
        int ij = m % (WIN * WIN);
        int ii = ij / WIN, jj = ij % WIN;
        ulonglong2 qa = *(const ulonglong2*)&s_qT[(w * WIN + ii) * QKP];
        ulonglong2 qb = *(const ulonglong2*)&s_qT[(w * WIN + ii) * QKP + 4];
        ulonglong2 ka = *(const ulonglong2*)&s_kT[(w * WIN + jj) * QKP];
        ulonglong2 kb = *(const ulonglong2*)&s_kT[(w * WIN + jj) * QKP + 4];
        u64 acc = fma2(qa.x, ka.x,
                  fma2(qa.y, ka.y,
                  fma2(qb.x, kb.x,
                  mul2(qb.y, kb.y))));
        s_att[w * AWS + ii * ARP + jj] = lo2(acc) + hi2(acc);
    }
    __syncthreads();

    // ---- softmax over 104 rows of length 13 (vectorized) ----
    if (tid < TP) {
        int w = tid / WIN, ii = tid % WIN;
        float* row = &s_att[w * AWS + ii * ARP];
        float4 ra = *(const float4*)row;
        float4 rb = *(const float4*)(row + 4);
        float4 rc = *(const float4*)(row + 8);
        float  rd = row[12];
        float m0 = fmaxf(fmaxf(fmaxf(ra.x, ra.y), fmaxf(ra.z, ra.w)),
                   fmaxf(fmaxf(fmaxf(rb.x, rb.y), fmaxf(rb.z, rb.w)),
                   fmaxf(fmaxf(fmaxf(rc.x, rc.y), fmaxf(rc.z, rc.w)), rd)));
        ra.x = __expf(ra.x - m0); ra.y = __expf(ra.y - m0);
        ra.z = __expf(ra.z - m0); ra.w = __expf(ra.w - m0);
        rb.x = __expf(rb.x - m0); rb.y = __expf(rb.y - m0);
        rb.z = __expf(rb.z - m0); rb.w = __expf(rb.w - m0);
        rc.x = __expf(rc.x - m0); rc.y = __expf(rc.y - m0);
        rc.z = __expf(rc.z - m0); rc.w = __expf(rc.w - m0);
        rd   = __expf(rd   - m0);
        float sum = ra.x + ra.y + ra.z + ra.w + rb.x + rb.y + rb.z + rb.w
                  + rc.x + rc.y + rc.z + rc.w + rd;
        float inv = __frcp_rn(sum);
        ra.x *= inv; ra.y *= inv; ra.z *= inv; ra.w *= inv;
        rb.x *= inv; rb.y *= inv; rb.z *= inv; rb.w *= inv;
        rc.x *= inv; rc.y *= inv; rc.z *= inv; rc.w *= inv;
        rd   *= inv;
        *(float4*)row       = ra;
        *(float4*)(row + 4) = rb;
        *(float4*)(row + 8) = rc;
        row[12] = rd;
    }
    __syncthreads();

    // ---- z = wv @ x (packed pairs along positions), 2ch x 13pos per thread ----
    {
        const int ct = tid >> 3;       // 0..31 channel pair
        const int pt = tid & 7;        // 0..7  window
        const int c0 = ct * 2;
        const int col0 = pt * PADW;

        u64 zp0[6], zp1[6];
        float z0s = 0.f, z1s = 0.f;
#pragma unroll
        for (int j = 0; j < 6; j++) { zp0[j] = 0ull; zp1[j] = 0ull; }

#pragma unroll 4
        for (int cc = 0; cc < CCH; cc++) {
            const float* xr = &s_xs[cc * XROW + col0];
            ulonglong2 xA = *(const ulonglong2*)xr;
            ulonglong2 xB = *(const ulonglong2*)(xr + 4);
            ulonglong2 xC = *(const ulonglong2*)(xr + 8);
            float x12 = xr[12];
            float2 wv2 = *(const float2*)&s_wvT[cc * WVP + c0];
            u64 w00 = dup2(wv2.x);
            u64 w11 = dup2(wv2.y);
            zp0[0] = fma2(w00, xA.x, zp0[0]); zp0[1] = fma2(w00, xA.y, zp0[1]);
            zp0[2] = fma2(w00, xB.x, zp0[2]); zp0[3] = fma2(w00, xB.y, zp0[3]);
            zp0[4] = fma2(w00, xC.x, zp0[4]); zp0[5] = fma2(w00, xC.y, zp0[5]);
            z0s = fmaf(wv2.x, x12, z0s);
            zp1[0] = fma2(w11, xA.x, zp1[0]); zp1[1] = fma2(w11, xA.y, zp1[1]);
            zp1[2] = fma2(w11, xB.x, zp1[2]); zp1[3] = fma2(w11, xB.y, zp1[3]);
            zp1[4] = fma2(w11, xC.x, zp1[4]); zp1[5] = fma2(w11, xC.y, zp1[5]);
            z1s = fmaf(wv2.y, x12, z1s);
        }

        // xs consumed by every thread; safe to alias as obuf after this barrier
        __syncthreads();

        // ---- out = z . att^T + bv -> staged in obuf (conflict-free scatter) ----
        const float* ar = &s_att[pt * AWS];
        const float bv0 = s_bv[c0], bv1 = s_bv[c0 + 1];
        float* ob0 = obuf + c0 * OBP + pt * WIN;
        float* ob1 = ob0 + OBP;
#pragma unroll
        for (int i = 0; i < WIN; i++) {
            const float* ari = ar + i * ARP;
            ulonglong2 aA = *(const ulonglong2*)ari;
            ulonglong2 aB = *(const ulonglong2*)(ari + 4);
            ulonglong2 aC = *(const ulonglong2*)(ari + 8);
            float a12 = ari[12];
            u64 s0 = fma2(zp0[0], aA.x,
                     fma2(zp0[1], aA.y,
                     fma2(zp0[2], aB.x,
                     fma2(zp0[3], aB.y,
                     fma2(zp0[4], aC.x,
                     mul2(zp0[5], aC.y))))));
            u64 s1 = fma2(zp1[0], aA.x,
                     fma2(zp1[1], aA.y,
                     fma2(zp1[2], aB.x,
                     fma2(zp1[3], aB.y,
                     fma2(zp1[4], aC.x,
                     mul2(zp1[5], aC.y))))));
            ob0[i] = lo2(s0) + hi2(s0) + fmaf(z0s, a12, bv0);
            ob1[i] = lo2(s1) + hi2(s1) + fmaf(z1s, a12, bv1);
        }
    }
    __syncthreads();

    // ---- coalesced global store: 64 rows x 104 floats as float4 ----
    for (int i = tid; i < CCH * (TP / 4); i += NTHREADS) {
        int r  = i / (TP / 4);
        int c4 = i % (TP / 4);
        float4 v = *reinterpret_cast<const float4*>(obuf + r * OBP + c4 * 4);
        *reinterpret_cast<float4*>(ob + (long)r * NVOX + c4 * 4) = v;
    }
}

extern "C" void kernel_launch(void* const* d_in, const int* in_sizes, int n_in,
                              void* d_out, int out_size) {
    const float* x  = (const float*)d_in[0];
    const float* wq = (const float*)d_in[1];
    const float* bq = (const float*)d_in[2];
    const float* wk = (const float*)d_in[3];
    const float* bk = (const float*)d_in[4];
    const float* wv = (const float*)d_in[5];
    const float* bv = (const float*)d_in[6];
    float* out = (float*)d_out;

    const int B = in_sizes[0] / (CCH * NVOX);   // 8

    static bool attr_set = false;
    if (!attr_set) {
        cudaFuncSetAttribute(win_attn_kernel,
                             cudaFuncAttributeMaxDynamicSharedMemorySize, SMEM_BYTES);
        attr_set = true;
    }

    dim3 grid(B * TILES_PER_B);
    win_attn_kernel<<<grid, NTHREADS, SMEM_BYTES>>>(x, wq, bq, wk, bk, wv, bv, out);
}

// round 9
// speedup vs baseline: 1.0101x; 1.0101x over previous
#include <cuda_runtime.h>
#include <cuda_bf16.h>
#include <cstdint>

#define CCH 64
#define CO 8
#define WIN 13
#define WPB 8
#define TP 104
#define NVOX 53248
#define TILES_PER_B 512
#define NTHREADS 256

#define HPOS 52          // positions per GEMM half
#define HNT 7            // n-tiles (of 8) per half; rows 52-55 of B zero-padded
#define NMT 5            // m-tiles of 16 -> 80 rows = [wv(64); wq(8); wk(8)]
#define APB 144          // A row pitch bytes (72 bf16) -> LDSM conflict-free
#define BPB 144          // B row pitch bytes
#define ZSP 108          // z smem pitch (words), R5-verified conflict-free scatter
#define QKPITCH 112      // q/k rows [ch][pos] pitch words
#define ARP 16           // att row pitch
#define AWS 208          // 13*ARP
#define OBP 108          // staged out pitch

// smem byte offsets (total 74304 -> 3 CTAs/SM)
#define OFF_AH   0       // 80*144 = 11520
#define OFF_AL   11520   // 11520 -> 23040
#define OFF_BH   23040   // 56*144 = 8064
#define OFF_BL   31104   // 8064 -> 39168  (GEMM region, dead after mainloop)
#define OFF_OBUF 0       // 27648 (aliases A)
#define OFF_ATT  27648   // 6656  (aliases A/B tail) -> 34304 <= 39168
#define OFF_Z    39168   // 64*108*4 = 27648 -> 66816
#define OFF_QS   66816   // 8*112*4 = 3584
#define OFF_KS   70400   // 3584 -> 73984
#define OFF_BQ   73984
#define OFF_BK   74016
#define OFF_BV   74048   // 256 -> 74304
#define SMEM_BYTES 74304

typedef unsigned long long u64;

__device__ __forceinline__ u64 fma2(u64 a, u64 b, u64 c) {
    u64 d; asm("fma.rn.f32x2 %0, %1, %2, %3;" : "=l"(d) : "l"(a), "l"(b), "l"(c));
    return d;
}
__device__ __forceinline__ u64 mul2(u64 a, u64 b) {
    u64 d; asm("mul.rn.f32x2 %0, %1, %2;" : "=l"(d) : "l"(a), "l"(b));
    return d;
}
__device__ __forceinline__ u64 pack2(float lo, float hi) {
    u64 d; asm("mov.b64 %0, {%1, %2};" : "=l"(d) : "f"(lo), "f"(hi));
    return d;
}
__device__ __forceinline__ float lo2(u64 v) { return __uint_as_float((unsigned)v); }
__device__ __forceinline__ float hi2(u64 v) { return __uint_as_float((unsigned)(v >> 32)); }

__device__ __forceinline__ uint32_t smem_u32(const void* p) {
    uint32_t a;
    asm("{ .reg .u64 t; cvta.to.shared.u64 t, %1; cvt.u32.u64 %0, t; }" : "=r"(a) : "l"(p));
    return a;
}
__device__ __forceinline__ void ldsm4(uint32_t* r, uint32_t addr) {
    asm volatile("ldmatrix.sync.aligned.m8n8.x4.shared.b16 {%0,%1,%2,%3}, [%4];"
                 : "=r"(r[0]), "=r"(r[1]), "=r"(r[2]), "=r"(r[3]) : "r"(addr));
}
__device__ __forceinline__ void mma16816(float* d, const uint32_t* a, const uint32_t* b) {
    asm volatile(
        "mma.sync.aligned.m16n8k16.row.col.f32.bf16.bf16.f32 "
        "{%0,%1,%2,%3}, {%4,%5,%6,%7}, {%8,%9}, {%0,%1,%2,%3};"
        : "+f"(d[0]), "+f"(d[1]), "+f"(d[2]), "+f"(d[3])
        : "r"(a[0]), "r"(a[1]), "r"(a[2]), "r"(a[3]), "r"(b[0]), "r"(b[1]));
}
__device__ __forceinline__ void split_pack(float v0, float v1, float v2, float v3,
                                           uint2& hp, uint2& lp) {
    __nv_bfloat16 h0 = __float2bfloat16(v0), h1 = __float2bfloat16(v1);
    __nv_bfloat16 h2 = __float2bfloat16(v2), h3 = __float2bfloat16(v3);
    __nv_bfloat16 l0 = __float2bfloat16(v0 - __bfloat162float(h0));
    __nv_bfloat16 l1 = __float2bfloat16(v1 - __bfloat162float(h1));
    __nv_bfloat16 l2 = __float2bfloat16(v2 - __bfloat162float(h2));
    __nv_bfloat16 l3 = __float2bfloat16(v3 - __bfloat162float(h3));
    hp.x = (unsigned)__bfloat16_as_ushort(h0) | ((unsigned)__bfloat16_as_ushort(h1) << 16);
    hp.y = (unsigned)__bfloat16_as_ushort(h2) | ((unsigned)__bfloat16_as_ushort(h3) << 16);
    lp.x = (unsigned)__bfloat16_as_ushort(l0) | ((unsigned)__bfloat16_as_ushort(l1) << 16);
    lp.y = (unsigned)__bfloat16_as_ushort(l2) | ((unsigned)__bfloat16_as_ushort(l3) << 16);
}

__global__ __launch_bounds__(NTHREADS, 3)
void win_attn_kernel(const float* __restrict__ x,
                     const float* __restrict__ wq, const float* __restrict__ bq,
                     const float* __restrict__ wk, const float* __restrict__ bk,
                     const float* __restrict__ wv, const float* __restrict__ bv,
                     float* __restrict__ out) {
    extern __shared__ char smem[];
    const uint32_t sb = smem_u32(smem);
    float* s_z   = (float*)(smem + OFF_Z);
    float* s_qs  = (float*)(smem + OFF_QS);
    float* s_ks  = (float*)(smem + OFF_KS);
    float* s_att = (float*)(smem + OFF_ATT);
    float* s_bq  = (float*)(smem + OFF_BQ);
    float* s_bk  = (float*)(smem + OFF_BK);
    float* s_bv  = (float*)(smem + OFF_BV);
    float* obuf  = (float*)(smem + OFF_OBUF);

    const int tid = threadIdx.x;
    const int wid = tid >> 5;
    const int lid = tid & 31;

    const int b    = blockIdx.x / TILES_PER_B;
    const int tile = blockIdx.x % TILES_PER_B;
    const long n0  = (long)tile * TP;
    const float* xb = x   + (long)b * CCH * NVOX + n0;
    float*       ob = out + (long)b * CCH * NVOX + n0;

    // ---- A = [wv;wq;wk] (80x64) -> bf16 hi/lo, pitch 144B ----
    for (int f = tid; f < 80 * 16; f += NTHREADS) {
        int row = f >> 4, c4 = f & 15;
        const float* src = (row < 64) ? (wv + row * 64 + c4 * 4)
                         : (row < 72) ? (wq + (row - 64) * 64 + c4 * 4)
                                      : (wk + (row - 72) * 64 + c4 * 4);
        float4 v = *(const float4*)src;
        uint2 hp, lp;
        split_pack(v.x, v.y, v.z, v.w, hp, lp);
        *(uint2*)(smem + OFF_AH + row * APB + c4 * 8) = hp;
        *(uint2*)(smem + OFF_AL + row * APB + c4 * 8) = lp;
    }
    // zero B pad rows 52-55 (hi & lo), once
    if (tid < 144) {
        ((uint32_t*)(smem + OFF_BH + 52 * BPB))[tid] = 0;
        ((uint32_t*)(smem + OFF_BL + 52 * BPB))[tid] = 0;
    }
    // ---- biases ----
    if (tid < CO)                      s_bq[tid]       = bq[tid];
    if (tid >= 64 && tid < 64 + CO)    s_bk[tid - 64]  = bk[tid - 64];
    if (tid >= 128 && tid < 128 + CCH) s_bv[tid - 128] = bv[tid - 128];
    // ---- B half 0: x^T [pos][ch] bf16 hi/lo ----
    for (int f = tid; f < HPOS * 16; f += NTHREADS) {
        int p = f % HPOS, cq = f / HPOS;
        const float* sp = xb + (long)(cq * 4) * NVOX + p;
        float v0 = sp[0], v1 = sp[(long)NVOX], v2 = sp[(long)NVOX * 2], v3 = sp[(long)NVOX * 3];
        uint2 hp, lp;
        split_pack(v0, v1, v2, v3, hp, lp);
        *(uint2*)(smem + OFF_BH + p * BPB + cq * 8) = hp;
        *(uint2*)(smem + OFF_BL + p * BPB + cq * 8) = lp;
    }
    __syncthreads();

    // ---- GEMM mainloop: D(80x104) = Ah Bh + Ah Bl + Al Bh via HMMA ----
    const uint32_t a_row  = (uint32_t)(lid & 15);
    const uint32_t a_colb = (uint32_t)(lid & 16);
    const uint32_t b_row  = (uint32_t)(lid & 7);
    const uint32_t b_colb = (uint32_t)((lid >> 3) * 16);

    for (int h = 0; h < 2; h++) {
        for (int t = wid; t < NMT * HNT; t += 8) {
            int m  = t / HNT;          // 0..4
            int nt = t % HNT;          // 0..6
            uint32_t aaddr_h = sb + OFF_AH + (16 * m + a_row) * APB + a_colb;
            uint32_t aaddr_l = sb + OFF_AL + (16 * m + a_row) * APB + a_colb;
            uint32_t baddr_h = sb + OFF_BH + (nt * 8 + b_row) * BPB + b_colb;
            uint32_t baddr_l = sb + OFF_BL + (nt * 8 + b_row) * BPB + b_colb;

            uint32_t bh[8], bl[8];
            ldsm4(bh,     baddr_h);        // k-tiles 0,1
            ldsm4(bh + 4, baddr_h + 64);   // k-tiles 2,3
            ldsm4(bl,     baddr_l);
            ldsm4(bl + 4, baddr_l + 64);

            float d[4] = {0.f, 0.f, 0.f, 0.f};
#pragma unroll
            for (int kt = 0; kt < 4; kt++) {
                uint32_t ah[4], al[4];
                ldsm4(ah, aaddr_h + kt * 32);
                ldsm4(al, aaddr_l + kt * 32);
                mma16816(d, ah, bh + 2 * kt);
                mma16816(d, ah, bl + 2 * kt);
                mma16816(d, al, bh + 2 * kt);
            }

            int col0 = h * HPOS + nt * 8 + 2 * (lid & 3);
            int r    = lid >> 2;                 // 0..7
            if (m < 4) {
                float2* z0 = (float2*)(s_z + (16 * m + r) * ZSP + col0);
                float2* z1 = (float2*)(s_z + (16 * m + r + 8) * ZSP + col0);
                *z0 = make_float2(d[0], d[1]);
                *z1 = make_float2(d[2], d[3]);
            } else {
                float bqv = s_bq[r], bkv = s_bk[r];
                *(float2*)(s_qs + r * QKPITCH + col0) = make_float2(d[0] + bqv, d[1] + bqv);
                *(float2*)(s_ks + r * QKPITCH + col0) = make_float2(d[2] + bkv, d[3] + bkv);
            }
        }
        __syncthreads();
        if (h == 0) {
            // reload B with half 1 positions
            for (int f = tid; f < HPOS * 16; f += NTHREADS) {
                int p = f % HPOS, cq = f / HPOS;
                const float* sp = xb + HPOS + (long)(cq * 4) * NVOX + p;
                float v0 = sp[0], v1 = sp[(long)NVOX], v2 = sp[(long)NVOX * 2], v3 = sp[(long)NVOX * 3];
                uint2 hp, lp;
                split_pack(v0, v1, v2, v3, hp, lp);
                *(uint2*)(smem + OFF_BH + p * BPB + cq * 8) = hp;
                *(uint2*)(smem + OFF_BL + p * BPB + cq * 8) = lp;
            }
            __syncthreads();
        }
    }

    // ---- scores: 8 windows x 13x13, q/k in [ch][pos] (biases already added) ----
    for (int m = tid; m < WPB * WIN * WIN; m += NTHREADS) {
        int w  = m / (WIN * WIN);
        int ij = m % (WIN * WIN);
        int ii = ij / WIN, jj = ij % WIN;
        int pi = w * WIN + ii, pj = w * WIN + jj;
        float acc = 0.f;
#pragma unroll
        for (int o = 0; o < CO; o++)
            acc = fmaf(s_qs[o * QKPITCH + pi], s_ks[o * QKPITCH + pj], acc);
        s_att[w * AWS + ii * ARP + jj] = acc;
    }
    __syncthreads();

    // ---- softmax over 104 rows of length 13 ----
    if (tid < TP) {
        int w = tid / WIN, ii = tid % WIN;
        float* row = &s_att[w * AWS + ii * ARP];
        float4 ra = *(const float4*)row;
        float4 rb = *(const float4*)(row + 4);
        float4 rc = *(const float4*)(row + 8);
        float  rd = row[12];
        float m0 = fmaxf(fmaxf(fmaxf(ra.x, ra.y), fmaxf(ra.z, ra.w)),
                   fmaxf(fmaxf(fmaxf(rb.x, rb.y), fmaxf(rb.z, rb.w)),
                   fmaxf(fmaxf(fmaxf(rc.x, rc.y), fmaxf(rc.z, rc.w)), rd)));
        ra.x = __expf(ra.x - m0); ra.y = __expf(ra.y - m0);
        ra.z = __expf(ra.z - m0); ra.w = __expf(ra.w - m0);
        rb.x = __expf(rb.x - m0); rb.y = __expf(rb.y - m0);
        rb.z = __expf(rb.z - m0); rb.w = __expf(rb.w - m0);
        rc.x = __expf(rc.x - m0); rc.y = __expf(rc.y - m0);
        rc.z = __expf(rc.z - m0); rc.w = __expf(rc.w - m0);
        rd   = __expf(rd   - m0);
        float sum = ra.x + ra.y + ra.z + ra.w + rb.x + rb.y + rb.z + rb.w
                  + rc.x + rc.y + rc.z + rc.w + rd;
        float inv = __frcp_rn(sum);
        ra.x *= inv; ra.y *= inv; ra.z *= inv; ra.w *= inv;
        rb.x *= inv; rb.y *= inv; rb.z *= inv; rb.w *= inv;
        rc.x *= inv; rc.y *= inv; rc.z *= inv; rc.w *= inv;
        rd   *= inv;
        *(float4*)row       = ra;
        *(float4*)(row + 4) = rb;
        *(float4*)(row + 8) = rc;
        row[12] = rd;
    }
    __syncthreads();

    // ---- att-apply: out = z . att^T + bv (z from smem), staged to obuf ----
    {
        const int ct = tid >> 3;       // 0..31 channel pair
        const int pt = tid & 7;        // 0..7  window
        const int c0 = ct * 2;

        const float* zr0 = s_z + c0 * ZSP + pt * WIN;
        const float* zr1 = zr0 + ZSP;
        float z0[WIN], z1[WIN];
#pragma unroll
        for (int j = 0; j < WIN; j++) { z0[j] = zr0[j]; z1[j] = zr1[j]; }

        u64 zp0[6], zp1[6];
#pragma unroll
        for (int q = 0; q < 6; q++) {
            zp0[q] = pack2(z0[2*q], z0[2*q + 1]);
            zp1[q] = pack2(z1[2*q], z1[2*q + 1]);
        }
        const float z0s = z0[12], z1s = z1[12];

        const float* ar = &s_att[pt * AWS];
        const float bv0 = s_bv[c0], bv1 = s_bv[c0 + 1];
        float* ob0 = obuf + c0 * OBP + pt * WIN;
        float* ob1 = ob0 + OBP;
#pragma unroll
        for (int i = 0; i < WIN; i++) {
            const float* ari = ar + i * ARP;
            ulonglong2 aA = *(const ulonglong2*)ari;
            ulonglong2 aB = *(const ulonglong2*)(ari + 4);
            ulonglong2 aC = *(const ulonglong2*)(ari + 8);
            float a12 = ari[12];
            u64 s0 = fma2(zp0[0], aA.x,
                     fma2(zp0[1], aA.y,
                     fma2(zp0[2], aB.x,
                     fma2(zp0[3], aB.y,
                     fma2(zp0[4], aC.x,
                     mul2(zp0[5], aC.y))))));
            u64 s1 = fma2(zp1[0], aA.x,
                     fma2(zp1[1], aA.y,
                     fma2(zp1[2], aB.x,
                     fma2(zp1[3], aB.y,
                     fma2(zp1[4], aC.x,
                     mul2(zp1[5], aC.y))))));
            ob0[i] = lo2(s0) + hi2(s0) + fmaf(z0s, a12, bv0);
            ob1[i] = lo2(s1) + hi2(s1) + fmaf(z1s, a12, bv1);
        }
    }
    __syncthreads();

    // ---- coalesced global store: 64 rows x 104 floats as float4 ----
    for (int i = tid; i < CCH * (TP / 4); i += NTHREADS) {
        int r  = i / (TP / 4);
        int c4 = i % (TP / 4);
        float4 v = *reinterpret_cast<const float4*>(obuf + r * OBP + c4 * 4);
        *reinterpret_cast<float4*>(ob + (long)r * NVOX + c4 * 4) = v;
    }
}

extern "C" void kernel_launch(void* const* d_in, const int* in_sizes, int n_in,
                              void* d_out, int out_size) {
    const float* x  = (const float*)d_in[0];
    const float* wq = (const float*)d_in[1];
    const float* bq = (const float*)d_in[2];
    const float* wk = (const float*)d_in[3];
    const float* bk = (const float*)d_in[4];
    const float* wv = (const float*)d_in[5];
    const float* bv = (const float*)d_in[6];
    float* out = (float*)d_out;

    const int B = in_sizes[0] / (CCH * NVOX);   // 8

    static bool attr_set = false;
    if (!attr_set) {
        cudaFuncSetAttribute(win_attn_kernel,
                             cudaFuncAttributeMaxDynamicSharedMemorySize, SMEM_BYTES);
        attr_set = true;
    }

    dim3 grid(B * TILES_PER_B);
    win_attn_kernel<<<grid, NTHREADS, SMEM_BYTES>>>(x, wq, bq, wk, bk, wv, bv, out);
}

// round 10
// speedup vs baseline: 1.0510x; 1.0404x over previous
#include <cuda_runtime.h>
#include <cuda_bf16.h>
#include <cstdint>

#define CCH 64
#define CO 8
#define WIN 13
#define WPB 8
#define TP 104
#define NVOX 53248
#define TILES_PER_B 512
#define NTHREADS 256

#define APB 272          // A row pitch bytes: [hi 128B | lo 128B + pad] (17*16, odd -> LDSM ok)
#define BPB 112          // B row pitch bytes (56 bf16 = exact half; 7 odd -> trans-LDSM ok)
#define ZSP 108          // z pitch words (verified conflict-free att-apply reads)
#define QKP 12           // qT/kT row pitch words
#define ARP 16           // att row pitch
#define AWS 208          // 13*ARP
#define OBP 108          // staged out pitch

// smem byte offsets (total 74048 -> 3 CTAs/SM)
#define OFF_A    0       // 80*272 = 21760
#define OFF_BH   21760   // 64*112 = 7168
#define OFF_BL   28928   // 7168 -> 36096 (GEMM region; dead after mainloop)
#define OFF_OBUF 0       // 27648 (aliases A+BH head)
#define OFF_ATT  27648   // 6656 -> 34304 (aliases BH tail/BL head)
#define OFF_Z    36096   // 64*108*4 = 27648 -> 63744
#define OFF_QT   63744   // 104*12*4 = 4992
#define OFF_KT   68736   // 4992 -> 73728
#define OFF_BQ   73728
#define OFF_BK   73760
#define OFF_BV   73792   // 256 -> 74048
#define SMEM_BYTES 74048

typedef unsigned long long u64;

__device__ __forceinline__ u64 fma2(u64 a, u64 b, u64 c) {
    u64 d; asm("fma.rn.f32x2 %0, %1, %2, %3;" : "=l"(d) : "l"(a), "l"(b), "l"(c));
    return d;
}
__device__ __forceinline__ u64 mul2(u64 a, u64 b) {
    u64 d; asm("mul.rn.f32x2 %0, %1, %2;" : "=l"(d) : "l"(a), "l"(b));
    return d;
}
__device__ __forceinline__ u64 pack2(float lo, float hi) {
    u64 d; asm("mov.b64 %0, {%1, %2};" : "=l"(d) : "f"(lo), "f"(hi));
    return d;
}
__device__ __forceinline__ float lo2(u64 v) { return __uint_as_float((unsigned)v); }
__device__ __forceinline__ float hi2(u64 v) { return __uint_as_float((unsigned)(v >> 32)); }

__device__ __forceinline__ uint32_t smem_u32(const void* p) {
    uint32_t a;
    asm("{ .reg .u64 t; cvta.to.shared.u64 t, %1; cvt.u32.u64 %0, t; }" : "=r"(a) : "l"(p));
    return a;
}
__device__ __forceinline__ void ldsm4(uint32_t* r, uint32_t addr) {
    asm volatile("ldmatrix.sync.aligned.m8n8.x4.shared.b16 {%0,%1,%2,%3}, [%4];"
                 : "=r"(r[0]), "=r"(r[1]), "=r"(r[2]), "=r"(r[3]) : "r"(addr));
}
__device__ __forceinline__ void ldsm4t(uint32_t* r, uint32_t addr) {
    asm volatile("ldmatrix.sync.aligned.m8n8.x4.trans.shared.b16 {%0,%1,%2,%3}, [%4];"
                 : "=r"(r[0]), "=r"(r[1]), "=r"(r[2]), "=r"(r[3]) : "r"(addr));
}
__device__ __forceinline__ void mma16816(float* d, const uint32_t* a, const uint32_t* b) {
    asm volatile(
        "mma.sync.aligned.m16n8k16.row.col.f32.bf16.bf16.f32 "
        "{%0,%1,%2,%3}, {%4,%5,%6,%7}, {%8,%9}, {%0,%1,%2,%3};"
        : "+f"(d[0]), "+f"(d[1]), "+f"(d[2]), "+f"(d[3])
        : "r"(a[0]), "r"(a[1]), "r"(a[2]), "r"(a[3]), "r"(b[0]), "r"(b[1]));
}
__device__ __forceinline__ void split_pack(float v0, float v1, float v2, float v3,
                                           uint2& hp, uint2& lp) {
    __nv_bfloat16 h0 = __float2bfloat16(v0), h1 = __float2bfloat16(v1);
    __nv_bfloat16 h2 = __float2bfloat16(v2), h3 = __float2bfloat16(v3);
    __nv_bfloat16 l0 = __float2bfloat16(v0 - __bfloat162float(h0));
    __nv_bfloat16 l1 = __float2bfloat16(v1 - __bfloat162float(h1));
    __nv_bfloat16 l2 = __float2bfloat16(v2 - __bfloat162float(h2));
    __nv_bfloat16 l3 = __float2bfloat16(v3 - __bfloat162float(h3));
    hp.x = (unsigned)__bfloat16_as_ushort(h0) | ((unsigned)__bfloat16_as_ushort(h1) << 16);
    hp.y = (unsigned)__bfloat16_as_ushort(h2) | ((unsigned)__bfloat16_as_ushort(h3) << 16);
    lp.x = (unsigned)__bfloat16_as_ushort(l0) | ((unsigned)__bfloat16_as_ushort(l1) << 16);
    lp.y = (unsigned)__bfloat16_as_ushort(l2) | ((unsigned)__bfloat16_as_ushort(l3) << 16);
}

__global__ __launch_bounds__(NTHREADS, 3)
void win_attn_kernel(const float* __restrict__ x,
                     const float* __restrict__ wq, const float* __restrict__ bq,
                     const float* __restrict__ wk, const float* __restrict__ bk,
                     const float* __restrict__ wv, const float* __restrict__ bv,
                     float* __restrict__ out) {
    extern __shared__ char smem[];
    const uint32_t sb = smem_u32(smem);
    float* s_z   = (float*)(smem + OFF_Z);
    float* s_qT  = (float*)(smem + OFF_QT);
    float* s_kT  = (float*)(smem + OFF_KT);
    float* s_att = (float*)(smem + OFF_ATT);
    float* s_bq  = (float*)(smem + OFF_BQ);
    float* s_bk  = (float*)(smem + OFF_BK);
    float* s_bv  = (float*)(smem + OFF_BV);
    float* obuf  = (float*)(smem + OFF_OBUF);

    const int tid = threadIdx.x;
    const int wid = tid >> 5;
    const int lid = tid & 31;

    const int b    = blockIdx.x / TILES_PER_B;
    const int tile = blockIdx.x % TILES_PER_B;
    const long n0  = (long)tile * TP;
    const float* xb = x   + (long)b * CCH * NVOX + n0;
    float*       ob = out + (long)b * CCH * NVOX + n0;

    // ---- A = [wv;wq;wk] (80x64) -> bf16 hi|lo packed per row, pitch 272B ----
    for (int f = tid; f < 80 * 16; f += NTHREADS) {
        int row = f >> 4, c4 = f & 15;
        const float* src = (row < 64) ? (wv + row * 64 + c4 * 4)
                         : (row < 72) ? (wq + (row - 64) * 64 + c4 * 4)
                                      : (wk + (row - 72) * 64 + c4 * 4);
        float4 v = *(const float4*)src;
        uint2 hp, lp;
        split_pack(v.x, v.y, v.z, v.w, hp, lp);
        *(uint2*)(smem + OFF_A + row * APB + c4 * 8) = hp;
        *(uint2*)(smem + OFF_A + row * APB + 128 + c4 * 8) = lp;
    }
    // ---- biases ----
    if (tid < CO)                      s_bq[tid]       = bq[tid];
    if (tid >= 64 && tid < 64 + CO)    s_bk[tid - 64]  = bk[tid - 64];
    if (tid >= 128 && tid < 128 + CCH) s_bv[tid - 128] = bv[tid - 128];
    // ---- B half 0: x [ch][pos 0..55] bf16 hi/lo, pitch 112B ----
    for (int f = tid; f < CCH * 14; f += NTHREADS) {
        int ch = f / 14, p4 = f % 14;
        float4 v = *(const float4*)(xb + (long)ch * NVOX + p4 * 4);
        uint2 hp, lp;
        split_pack(v.x, v.y, v.z, v.w, hp, lp);
        *(uint2*)(smem + OFF_BH + ch * BPB + p4 * 8) = hp;
        *(uint2*)(smem + OFF_BL + ch * BPB + p4 * 8) = lp;
    }
    __syncthreads();

    // ---- GEMM: D(80x104) = Ah Bh + Ah Bl + Al Bh, two 56-pos halves ----
    // units: u = (m<<1)|ng ; ng0 -> nt 0..3, ng1 -> nt 4..6. warp w: unit w;
    // warps 0,1 additionally take units 8,9 (m=4).
    const int u0 = wid;
    const int u1 = (wid < 2) ? 8 + wid : -1;
    const uint32_t arow = sb + OFF_A + (uint32_t)(lid & 15) * APB + (uint32_t)(lid & 16);

    for (int h = 0; h < 2; h++) {
        if (h == 1) {
            __syncthreads();   // everyone done reading B half 0
            for (int f = tid; f < CCH * 14; f += NTHREADS) {
                int ch = f / 14, p4 = f % 14;
                float4 v = *(const float4*)(xb + (long)ch * NVOX + 48 + p4 * 4);
                uint2 hp, lp;
                split_pack(v.x, v.y, v.z, v.w, hp, lp);
                *(uint2*)(smem + OFF_BH + ch * BPB + p4 * 8) = hp;
                *(uint2*)(smem + OFF_BL + ch * BPB + p4 * 8) = lp;
            }
            __syncthreads();
        }
#pragma unroll
        for (int uu = 0; uu < 2; uu++) {
            int u = (uu == 0) ? u0 : u1;
            if (u < 0) continue;
            int m = u >> 1, ng = u & 1;
            int ntBeg = ng * 4, ntCnt = ng ? 3 : 4;

            float d[16];
#pragma unroll
            for (int i = 0; i < 16; i++) d[i] = 0.f;

            uint32_t aaddr = arow + (uint32_t)(16 * m) * APB;
#pragma unroll
            for (int ktp = 0; ktp < 2; ktp++) {
                uint32_t ah[8], al[8];
                ldsm4(ah,     aaddr + ktp * 64);
                ldsm4(ah + 4, aaddr + ktp * 64 + 32);
                ldsm4(al,     aaddr + 128 + ktp * 64);
                ldsm4(al + 4, aaddr + 128 + ktp * 64 + 32);
                uint32_t brow = sb + (uint32_t)(ktp * 32 + lid) * BPB;
                for (int j = 0; j < ntCnt; j++) {
                    int nt = ntBeg + j;
                    uint32_t bh[4], bl[4];
                    ldsm4t(bh, brow + OFF_BH + nt * 16);
                    ldsm4t(bl, brow + OFF_BL + nt * 16);
                    float* dj = d + 4 * j;
                    mma16816(dj, ah,     bh);
                    mma16816(dj, ah,     bl);
                    mma16816(dj, al,     bh);
                    mma16816(dj, ah + 4, bh + 2);
                    mma16816(dj, ah + 4, bl + 2);
                    mma16816(dj, al + 4, bh + 2);
                }
            }

            // epilogue
            int r = lid >> 2;
            for (int j = 0; j < ntCnt; j++) {
                int nt = ntBeg + j;
                int gp = h * 48 + nt * 8 + 2 * (lid & 3);
                float* dj = d + 4 * j;
                if (m < 4) {
                    *(float2*)(s_z + (16 * m + r) * ZSP + gp)     = make_float2(dj[0], dj[1]);
                    *(float2*)(s_z + (16 * m + r + 8) * ZSP + gp) = make_float2(dj[2], dj[3]);
                } else {
                    float bqv = s_bq[r], bkv = s_bk[r];
                    s_qT[gp * QKP + r]       = dj[0] + bqv;
                    s_qT[(gp + 1) * QKP + r] = dj[1] + bqv;
                    s_kT[gp * QKP + r]       = dj[2] + bkv;
                    s_kT[(gp + 1) * QKP + r] = dj[3] + bkv;
                }
            }
        }
    }
    __syncthreads();

    // ---- scores: 8 windows x 13x13, packed dot over 8 q/k channels ----
    for (int m = tid; m < WPB * WIN * WIN; m += NTHREADS) {
        int w  = m / (WIN * WIN);
        int ij = m % (WIN * WIN);
        int ii = ij / WIN, jj = ij % WIN;
        ulonglong2 qa = *(const ulonglong2*)&s_qT[(w * WIN + ii) * QKP];
        ulonglong2 qb = *(const ulonglong2*)&s_qT[(w * WIN + ii) * QKP + 4];
        ulonglong2 ka = *(const ulonglong2*)&s_kT[(w * WIN + jj) * QKP];
        ulonglong2 kb = *(const ulonglong2*)&s_kT[(w * WIN + jj) * QKP + 4];
        u64 acc = fma2(qa.x, ka.x,
                  fma2(qa.y, ka.y,
                  fma2(qb.x, kb.x,
                  mul2(qb.y, kb.y))));
        s_att[w * AWS + ii * ARP + jj] = lo2(acc) + hi2(acc);
    }
    __syncthreads();

    // ---- softmax over 104 rows of length 13 ----
    if (tid < TP) {
        int w = tid / WIN, ii = tid % WIN;
        float* row = &s_att[w * AWS + ii * ARP];
        float4 ra = *(const float4*)row;
        float4 rb = *(const float4*)(row + 4);
        float4 rc = *(const float4*)(row + 8);
        float  rd = row[12];
        float m0 = fmaxf(fmaxf(fmaxf(ra.x, ra.y), fmaxf(ra.z, ra.w)),
                   fmaxf(fmaxf(fmaxf(rb.x, rb.y), fmaxf(rb.z, rb.w)),
                   fmaxf(fmaxf(fmaxf(rc.x, rc.y), fmaxf(rc.z, rc.w)), rd)));
        ra.x = __expf(ra.x - m0); ra.y = __expf(ra.y - m0);
        ra.z = __expf(ra.z - m0); ra.w = __expf(ra.w - m0);
        rb.x = __expf(rb.x - m0); rb.y = __expf(rb.y - m0);
        rb.z = __expf(rb.z - m0); rb.w = __expf(rb.w - m0);
        rc.x = __expf(rc.x - m0); rc.y = __expf(rc.y - m0);
        rc.z = __expf(rc.z - m0); rc.w = __expf(rc.w - m0);
        rd   = __expf(rd   - m0);
        float sum = ra.x + ra.y + ra.z + ra.w + rb.x + rb.y + rb.z + rb.w
                  + rc.x + rc.y + rc.z + rc.w + rd;
        float inv = __frcp_rn(sum);
        ra.x *= inv; ra.y *= inv; ra.z *= inv; ra.w *= inv;
        rb.x *= inv; rb.y *= inv; rb.z *= inv; rb.w *= inv;
        rc.x *= inv; rc.y *= inv; rc.z *= inv; rc.w *= inv;
        rd   *= inv;
        *(float4*)row       = ra;
        *(float4*)(row + 4) = rb;
        *(float4*)(row + 8) = rc;
        row[12] = rd;
    }
    __syncthreads();

    // ---- att-apply: out = z . att^T + bv (z/att from smem), staged to obuf ----
    {
        const int ct = tid >> 3;       // 0..31 channel pair
        const int pt = tid & 7;        // 0..7  window
        const int c0 = ct * 2;

        const float* zr0 = s_z + c0 * ZSP + pt * WIN;
        const float* zr1 = zr0 + ZSP;
        float z0[WIN], z1[WIN];
#pragma unroll
        for (int j = 0; j < WIN; j++) { z0[j] = zr0[j]; z1[j] = zr1[j]; }

        u64 zp0[6], zp1[6];
#pragma unroll
        for (int q = 0; q < 6; q++) {
            zp0[q] = pack2(z0[2*q], z0[2*q + 1]);
            zp1[q] = pack2(z1[2*q], z1[2*q + 1]);
        }
        const float z0s = z0[12], z1s = z1[12];

        const float* ar = &s_att[pt * AWS];
        const float bv0 = s_bv[c0], bv1 = s_bv[c0 + 1];
        float* ob0 = obuf + c0 * OBP + pt * WIN;
        float* ob1 = ob0 + OBP;
#pragma unroll
        for (int i = 0; i < WIN; i++) {
            const float* ari = ar + i * ARP;
            ulonglong2 aA = *(const ulonglong2*)ari;
            ulonglong2 aB = *(const ulonglong2*)(ari + 4);
            ulonglong2 aC = *(const ulonglong2*)(ari + 8);
            float a12 = ari[12];
            u64 s0 = fma2(zp0[0], aA.x,
                     fma2(zp0[1], aA.y,
                     fma2(zp0[2], aB.x,
                     fma2(zp0[3], aB.y,
                     fma2(zp0[4], aC.x,
                     mul2(zp0[5], aC.y))))));
            u64 s1 = fma2(zp1[0], aA.x,
                     fma2(zp1[1], aA.y,
                     fma2(zp1[2], aB.x,
                     fma2(zp1[3], aB.y,
                     fma2(zp1[4], aC.x,
                     mul2(zp1[5], aC.y))))));
            ob0[i] = lo2(s0) + hi2(s0) + fmaf(z0s, a12, bv0);
            ob1[i] = lo2(s1) + hi2(s1) + fmaf(z1s, a12, bv1);
        }
    }
    __syncthreads();

    // ---- coalesced global store: 64 rows x 104 floats as float4 ----
    for (int i = tid; i < CCH * (TP / 4); i += NTHREADS) {
        int r  = i / (TP / 4);
        int c4 = i % (TP / 4);
        float4 v = *reinterpret_cast<const float4*>(obuf + r * OBP + c4 * 4);
        *reinterpret_cast<float4*>(ob + (long)r * NVOX + c4 * 4) = v;
    }
}

extern "C" void kernel_launch(void* const* d_in, const int* in_sizes, int n_in,
                              void* d_out, int out_size) {
    const float* x  = (const float*)d_in[0];
    const float* wq = (const float*)d_in[1];
    const float* bq = (const float*)d_in[2];
    const float* wk = (const float*)d_in[3];
    const float* bk = (const float*)d_in[4];
    const float* wv = (const float*)d_in[5];
    const float* bv = (const float*)d_in[6];
    float* out = (float*)d_out;

    const int B = in_sizes[0] / (CCH * NVOX);   // 8

    static bool attr_set = false;
    if (!attr_set) {
        cudaFuncSetAttribute(win_attn_kernel,
                             cudaFuncAttributeMaxDynamicSharedMemorySize, SMEM_BYTES);
        attr_set = true;
    }

    dim3 grid(B * TILES_PER_B);
    win_attn_kernel<<<grid, NTHREADS, SMEM_BYTES>>>(x, wq, bq, wk, bk, wv, bv, out);
}

// round 11
// speedup vs baseline: 1.4701x; 1.3988x over previous
#include <cuda_runtime.h>
#include <cuda_bf16.h>
#include <cstdint>

#define CCH 64
#define CO 8
#define WIN 13
#define WPB 8
#define TP 104
#define NVOX 53248
#define TILES_PER_B 512
#define NTHREADS 256

#define APB 272          // A row pitch bytes: [hi 128B | lo 128B + pad]
#define BPB 112          // B row pitch bytes
#define ZSP 108          // z pitch words
#define QKP 12           // qT/kT row pitch words
#define ARP 16           // att row pitch words
#define AWS 212          // att window stride words: 212*pt mod 32 all-distinct banks
#define OBP 108          // staged out pitch

// smem byte offsets (total 74048 -> 3 CTAs/SM)
#define OFF_A    0       // 80*272 = 21760
#define OFF_BH   21760   // 64*112 = 7168
#define OFF_BL   28928   // 7168 -> 36096 (GEMM region; dead after mainloop)
#define OFF_OBUF 0       // 27648 (aliases A)
#define OFF_ATT  27648   // 8*212*4 = 6784 -> 34432 (aliases BH tail/BL; used post-GEMM)
#define OFF_Z    36096   // 64*108*4 = 27648 -> 63744
#define OFF_QT   63744   // 104*12*4 = 4992
#define OFF_KT   68736   // 4992 -> 73728
#define OFF_BQ   73728
#define OFF_BK   73760
#define OFF_BV   73792   // 256 -> 74048
#define SMEM_BYTES 74048

typedef unsigned long long u64;

__device__ __forceinline__ u64 fma2(u64 a, u64 b, u64 c) {
    u64 d; asm("fma.rn.f32x2 %0, %1, %2, %3;" : "=l"(d) : "l"(a), "l"(b), "l"(c));
    return d;
}
__device__ __forceinline__ u64 mul2(u64 a, u64 b) {
    u64 d; asm("mul.rn.f32x2 %0, %1, %2;" : "=l"(d) : "l"(a), "l"(b));
    return d;
}
__device__ __forceinline__ u64 pack2(float lo, float hi) {
    u64 d; asm("mov.b64 %0, {%1, %2};" : "=l"(d) : "f"(lo), "f"(hi));
    return d;
}
__device__ __forceinline__ float lo2(u64 v) { return __uint_as_float((unsigned)v); }
__device__ __forceinline__ float hi2(u64 v) { return __uint_as_float((unsigned)(v >> 32)); }

__device__ __forceinline__ uint32_t smem_u32(const void* p) {
    uint32_t a;
    asm("{ .reg .u64 t; cvta.to.shared.u64 t, %1; cvt.u32.u64 %0, t; }" : "=r"(a) : "l"(p));
    return a;
}
__device__ __forceinline__ void ldsm4(uint32_t* r, uint32_t addr) {
    asm volatile("ldmatrix.sync.aligned.m8n8.x4.shared.b16 {%0,%1,%2,%3}, [%4];"
                 : "=r"(r[0]), "=r"(r[1]), "=r"(r[2]), "=r"(r[3]) : "r"(addr));
}
__device__ __forceinline__ void ldsm4t(uint32_t* r, uint32_t addr) {
    asm volatile("ldmatrix.sync.aligned.m8n8.x4.trans.shared.b16 {%0,%1,%2,%3}, [%4];"
                 : "=r"(r[0]), "=r"(r[1]), "=r"(r[2]), "=r"(r[3]) : "r"(addr));
}
__device__ __forceinline__ void mma16816(float* d, const uint32_t* a, const uint32_t* b) {
    asm volatile(
        "mma.sync.aligned.m16n8k16.row.col.f32.bf16.bf16.f32 "
        "{%0,%1,%2,%3}, {%4,%5,%6,%7}, {%8,%9}, {%0,%1,%2,%3};"
        : "+f"(d[0]), "+f"(d[1]), "+f"(d[2]), "+f"(d[3])
        : "r"(a[0]), "r"(a[1]), "r"(a[2]), "r"(a[3]), "r"(b[0]), "r"(b[1]));
}
__device__ __forceinline__ void split_pack(float v0, float v1, float v2, float v3,
                                           uint2& hp, uint2& lp) {
    __nv_bfloat16 h0 = __float2bfloat16(v0), h1 = __float2bfloat16(v1);
    __nv_bfloat16 h2 = __float2bfloat16(v2), h3 = __float2bfloat16(v3);
    __nv_bfloat16 l0 = __float2bfloat16(v0 - __bfloat162float(h0));
    __nv_bfloat16 l1 = __float2bfloat16(v1 - __bfloat162float(h1));
    __nv_bfloat16 l2 = __float2bfloat16(v2 - __bfloat162float(h2));
    __nv_bfloat16 l3 = __float2bfloat16(v3 - __bfloat162float(h3));
    hp.x = (unsigned)__bfloat16_as_ushort(h0) | ((unsigned)__bfloat16_as_ushort(h1) << 16);
    hp.y = (unsigned)__bfloat16_as_ushort(h2) | ((unsigned)__bfloat16_as_ushort(h3) << 16);
    lp.x = (unsigned)__bfloat16_as_ushort(l0) | ((unsigned)__bfloat16_as_ushort(l1) << 16);
    lp.y = (unsigned)__bfloat16_as_ushort(l2) | ((unsigned)__bfloat16_as_ushort(l3) << 16);
}

// One (m, nt-group) GEMM unit with compile-time NT so the j-loop fully unrolls.
template<int NT>
__device__ __forceinline__ void gemm_unit(
    const uint32_t sb, char* smem, int h, int m, int ntBeg, int lid)
{
    float* s_z  = (float*)(smem + OFF_Z);
    float* s_qT = (float*)(smem + OFF_QT);
    float* s_kT = (float*)(smem + OFF_KT);
    float* s_bq = (float*)(smem + OFF_BQ);
    float* s_bk = (float*)(smem + OFF_BK);

    float d[NT * 4];
#pragma unroll
    for (int i = 0; i < NT * 4; i++) d[i] = 0.f;

    const uint32_t arow  = sb + OFF_A + (uint32_t)(lid & 15) * APB + (uint32_t)(lid & 16);
    const uint32_t aaddr = arow + (uint32_t)(16 * m) * APB;

#pragma unroll
    for (int ktp = 0; ktp < 2; ktp++) {
        uint32_t ah[8], al[8];
        ldsm4(ah,     aaddr + ktp * 64);
        ldsm4(ah + 4, aaddr + ktp * 64 + 32);
        ldsm4(al,     aaddr + 128 + ktp * 64);
        ldsm4(al + 4, aaddr + 128 + ktp * 64 + 32);
        uint32_t brow = sb + (uint32_t)(ktp * 32 + lid) * BPB;
#pragma unroll
        for (int j = 0; j < NT; j++) {
            int nt = ntBeg + j;
            uint32_t bh[4], bl[4];
            ldsm4t(bh, brow + OFF_BH + nt * 16);
            ldsm4t(bl, brow + OFF_BL + nt * 16);
            float* dj = d + 4 * j;
            mma16816(dj, ah,     bh);
            mma16816(dj, ah,     bl);
            mma16816(dj, al,     bh);
            mma16816(dj, ah + 4, bh + 2);
            mma16816(dj, ah + 4, bl + 2);
            mma16816(dj, al + 4, bh + 2);
        }
    }

    // epilogue
    int r = lid >> 2;
#pragma unroll
    for (int j = 0; j < NT; j++) {
        int nt = ntBeg + j;
        int gp = h * 48 + nt * 8 + 2 * (lid & 3);
        float* dj = d + 4 * j;
        if (m < 4) {
            *(float2*)(s_z + (16 * m + r) * ZSP + gp)     = make_float2(dj[0], dj[1]);
            *(float2*)(s_z + (16 * m + r + 8) * ZSP + gp) = make_float2(dj[2], dj[3]);
        } else {
            float bqv = s_bq[r], bkv = s_bk[r];
            s_qT[gp * QKP + r]       = dj[0] + bqv;
            s_qT[(gp + 1) * QKP + r] = dj[1] + bqv;
            s_kT[gp * QKP + r]       = dj[2] + bkv;
            s_kT[(gp + 1) * QKP + r] = dj[3] + bkv;
        }
    }
}

__global__ __launch_bounds__(NTHREADS, 3)
void win_attn_kernel(const float* __restrict__ x,
                     const float* __restrict__ wq, const float* __restrict__ bq,
                     const float* __restrict__ wk, const float* __restrict__ bk,
                     const float* __restrict__ wv, const float* __restrict__ bv,
                     float* __restrict__ out) {
    extern __shared__ char smem[];
    const uint32_t sb = smem_u32(smem);
    float* s_z   = (float*)(smem + OFF_Z);
    float* s_qT  = (float*)(smem + OFF_QT);
    float* s_kT  = (float*)(smem + OFF_KT);
    float* s_att = (float*)(smem + OFF_ATT);
    float* s_bq  = (float*)(smem + OFF_BQ);
    float* s_bk  = (float*)(smem + OFF_BK);
    float* s_bv  = (float*)(smem + OFF_BV);
    float* obuf  = (float*)(smem + OFF_OBUF);

    const int tid = threadIdx.x;
    const int wid = tid >> 5;
    const int lid = tid & 31;

    const int b    = blockIdx.x / TILES_PER_B;
    const int tile = blockIdx.x % TILES_PER_B;
    const long n0  = (long)tile * TP;
    const float* xb = x   + (long)b * CCH * NVOX + n0;
    float*       ob = out + (long)b * CCH * NVOX + n0;

    // ---- A = [wv;wq;wk] (80x64) -> bf16 hi|lo packed per row, pitch 272B ----
    for (int f = tid; f < 80 * 16; f += NTHREADS) {
        int row = f >> 4, c4 = f & 15;
        const float* src = (row < 64) ? (wv + row * 64 + c4 * 4)
                         : (row < 72) ? (wq + (row - 64) * 64 + c4 * 4)
                                      : (wk + (row - 72) * 64 + c4 * 4);
        float4 v = *(const float4*)src;
        uint2 hp, lp;
        split_pack(v.x, v.y, v.z, v.w, hp, lp);
        *(uint2*)(smem + OFF_A + row * APB + c4 * 8) = hp;
        *(uint2*)(smem + OFF_A + row * APB + 128 + c4 * 8) = lp;
    }
    // ---- biases ----
    if (tid < CO)                      s_bq[tid]       = bq[tid];
    if (tid >= 64 && tid < 64 + CO)    s_bk[tid - 64]  = bk[tid - 64];
    if (tid >= 128 && tid < 128 + CCH) s_bv[tid - 128] = bv[tid - 128];
    // ---- B half 0: x [ch][pos 0..55] bf16 hi/lo, pitch 112B ----
    for (int f = tid; f < CCH * 14; f += NTHREADS) {
        int ch = f / 14, p4 = f % 14;
        float4 v = *(const float4*)(xb + (long)ch * NVOX + p4 * 4);
        uint2 hp, lp;
        split_pack(v.x, v.y, v.z, v.w, hp, lp);
        *(uint2*)(smem + OFF_BH + ch * BPB + p4 * 8) = hp;
        *(uint2*)(smem + OFF_BL + ch * BPB + p4 * 8) = lp;
    }
    __syncthreads();

    // ---- GEMM: D(80x104) = Ah Bh + Ah Bl + Al Bh, two 56-pos halves ----
    const int mA = wid >> 1;
    const int ng = wid & 1;

    for (int h = 0; h < 2; h++) {
        if (h == 1) {
            __syncthreads();   // everyone done reading B half 0
            for (int f = tid; f < CCH * 14; f += NTHREADS) {
                int ch = f / 14, p4 = f % 14;
                float4 v = *(const float4*)(xb + (long)ch * NVOX + 48 + p4 * 4);
                uint2 hp, lp;
                split_pack(v.x, v.y, v.z, v.w, hp, lp);
                *(uint2*)(smem + OFF_BH + ch * BPB + p4 * 8) = hp;
                *(uint2*)(smem + OFF_BL + ch * BPB + p4 * 8) = lp;
            }
            __syncthreads();
        }
        if (wid == 0) {
            gemm_unit<4>(sb, smem, h, 0, 0, lid);
            gemm_unit<4>(sb, smem, h, 4, 0, lid);
        } else if (wid == 1) {
            gemm_unit<3>(sb, smem, h, 0, 4, lid);
            gemm_unit<3>(sb, smem, h, 4, 4, lid);
        } else if (ng == 0) {
            gemm_unit<4>(sb, smem, h, mA, 0, lid);
        } else {
            gemm_unit<3>(sb, smem, h, mA, 4, lid);
        }
    }
    __syncthreads();

    // ---- scores: 8 windows x 13x13, packed dot over 8 q/k channels ----
    for (int m = tid; m < WPB * WIN * WIN; m += NTHREADS) {
        int w  = m / (WIN * WIN);
        int ij = m % (WIN * WIN);
        int ii = ij / WIN, jj = ij % WIN;
        ulonglong2 qa = *(const ulonglong2*)&s_qT[(w * WIN + ii) * QKP];
        ulonglong2 qb = *(const ulonglong2*)&s_qT[(w * WIN + ii) * QKP + 4];
        ulonglong2 ka = *(const ulonglong2*)&s_kT[(w * WIN + jj) * QKP];
        ulonglong2 kb = *(const ulonglong2*)&s_kT[(w * WIN + jj) * QKP + 4];
        u64 acc = fma2(qa.x, ka.x,
                  fma2(qa.y, ka.y,
                  fma2(qb.x, kb.x,
                  mul2(qb.y, kb.y))));
        s_att[w * AWS + ii * ARP + jj] = lo2(acc) + hi2(acc);
    }
    __syncthreads();

    // ---- softmax over 104 rows of length 13 ----
    if (tid < TP) {
        int w = tid / WIN, ii = tid % WIN;
        float* row = &s_att[w * AWS + ii * ARP];
        float4 ra = *(const float4*)row;
        float4 rb = *(const float4*)(row + 4);
        float4 rc = *(const float4*)(row + 8);
        float  rd = row[12];
        float m0 = fmaxf(fmaxf(fmaxf(ra.x, ra.y), fmaxf(ra.z, ra.w)),
                   fmaxf(fmaxf(fmaxf(rb.x, rb.y), fmaxf(rb.z, rb.w)),
                   fmaxf(fmaxf(fmaxf(rc.x, rc.y), fmaxf(rc.z, rc.w)), rd)));
        ra.x = __expf(ra.x - m0); ra.y = __expf(ra.y - m0);
        ra.z = __expf(ra.z - m0); ra.w = __expf(ra.w - m0);
        rb.x = __expf(rb.x - m0); rb.y = __expf(rb.y - m0);
        rb.z = __expf(rb.z - m0); rb.w = __expf(rb.w - m0);
        rc.x = __expf(rc.x - m0); rc.y = __expf(rc.y - m0);
        rc.z = __expf(rc.z - m0); rc.w = __expf(rc.w - m0);
        rd   = __expf(rd   - m0);
        float sum = ra.x + ra.y + ra.z + ra.w + rb.x + rb.y + rb.z + rb.w
                  + rc.x + rc.y + rc.z + rc.w + rd;
        float inv = __frcp_rn(sum);
        ra.x *= inv; ra.y *= inv; ra.z *= inv; ra.w *= inv;
        rb.x *= inv; rb.y *= inv; rb.z *= inv; rb.w *= inv;
        rc.x *= inv; rc.y *= inv; rc.z *= inv; rc.w *= inv;
        rd   *= inv;
        *(float4*)row       = ra;
        *(float4*)(row + 4) = rb;
        *(float4*)(row + 8) = rc;
        row[12] = rd;
    }
    __syncthreads();

    // ---- att-apply: out = z . att^T + bv (z/att from smem), staged to obuf ----
    {
        const int ct = tid >> 3;       // 0..31 channel pair
        const int pt = tid & 7;        // 0..7  window
        const int c0 = ct * 2;

        const float* zr0 = s_z + c0 * ZSP + pt * WIN;
        const float* zr1 = zr0 + ZSP;
        float z0[WIN], z1[WIN];
#pragma unroll
        for (int j = 0; j < WIN; j++) { z0[j] = zr0[j]; z1[j] = zr1[j]; }

        u64 zp0[6], zp1[6];
#pragma unroll
        for (int q = 0; q < 6; q++) {
            zp0[q] = pack2(z0[2*q], z0[2*q + 1]);
            zp1[q] = pack2(z1[2*q], z1[2*q + 1]);
        }
        const float z0s = z0[12], z1s = z1[12];

        const float* ar = &s_att[pt * AWS];
        const float bv0 = s_bv[c0], bv1 = s_bv[c0 + 1];
        float* ob0 = obuf + c0 * OBP + pt * WIN;
        float* ob1 = ob0 + OBP;
#pragma unroll
        for (int i = 0; i < WIN; i++) {
            const float* ari = ar + i * ARP;
            ulonglong2 aA = *(const ulonglong2*)ari;
            ulonglong2 aB = *(const ulonglong2*)(ari + 4);
            ulonglong2 aC = *(const ulonglong2*)(ari + 8);
            float a12 = ari[12];
            u64 s0 = fma2(zp0[0], aA.x,
                     fma2(zp0[1], aA.y,
                     fma2(zp0[2], aB.x,
                     fma2(zp0[3], aB.y,
                     fma2(zp0[4], aC.x,
                     mul2(zp0[5], aC.y))))));
            u64 s1 = fma2(zp1[0], aA.x,
                     fma2(zp1[1], aA.y,
                     fma2(zp1[2], aB.x,
                     fma2(zp1[3], aB.y,
                     fma2(zp1[4], aC.x,
                     mul2(zp1[5], aC.y))))));
            ob0[i] = lo2(s0) + hi2(s0) + fmaf(z0s, a12, bv0);
            ob1[i] = lo2(s1) + hi2(s1) + fmaf(z1s, a12, bv1);
        }
    }
    __syncthreads();

    // ---- coalesced global store: 64 rows x 104 floats as float4 ----
    for (int i = tid; i < CCH * (TP / 4); i += NTHREADS) {
        int r  = i / (TP / 4);
        int c4 = i % (TP / 4);
        float4 v = *reinterpret_cast<const float4*>(obuf + r * OBP + c4 * 4);
        *reinterpret_cast<float4*>(ob + (long)r * NVOX + c4 * 4) = v;
    }
}

extern "C" void kernel_launch(void* const* d_in, const int* in_sizes, int n_in,
                              void* d_out, int out_size) {
    const float* x  = (const float*)d_in[0];
    const float* wq = (const float*)d_in[1];
    const float* bq = (const float*)d_in[2];
    const float* wk = (const float*)d_in[3];
    const float* bk = (const float*)d_in[4];
    const float* wv = (const float*)d_in[5];
    const float* bv = (const float*)d_in[6];
    float* out = (float*)d_out;

    const int B = in_sizes[0] / (CCH * NVOX);   // 8

    static bool attr_set = false;
    if (!attr_set) {
        cudaFuncSetAttribute(win_attn_kernel,
                             cudaFuncAttributeMaxDynamicSharedMemorySize, SMEM_BYTES);
        attr_set = true;
    }

    dim3 grid(B * TILES_PER_B);
    win_attn_kernel<<<grid, NTHREADS, SMEM_BYTES>>>(x, wq, bq, wk, bk, wv, bv, out);
}